// round 5
// baseline (speedup 1.0000x reference)
#include <cuda_runtime.h>

// Problem constants
#define HW      16384      // 128*128
#define CIN     512
#define CH      30
#define NPAIR   15         // 30 channels as 15 f32x2 pairs
#define NCLS    17
#define NBATCH  8
#define BN_EPS  1e-5f
#define TPB     256
#define PF      8          // prefetch depth (x channels in flight per thread)

typedef unsigned long long u64;

// ---- packed f32x2 helpers (Blackwell sm_100a: fma.rn.f32x2) ----
__device__ __forceinline__ u64 fma2(u64 a, u64 b, u64 c) {
    u64 d;
    asm("fma.rn.f32x2 %0, %1, %2, %3;" : "=l"(d) : "l"(a), "l"(b), "l"(c));
    return d;
}
__device__ __forceinline__ u64 dup2(float v) {
    u64 d;
    asm("mov.b64 %0, {%1, %1};" : "=l"(d) : "f"(v));
    return d;
}
__device__ __forceinline__ u64 pack2(float lo, float hi) {
    u64 d;
    asm("mov.b64 %0, {%1, %2};" : "=l"(d) : "f"(lo), "f"(hi));
    return d;
}
__device__ __forceinline__ float2 unpack2(u64 v) {
    float lo, hi;
    asm("mov.b64 {%0, %1}, %2;" : "=f"(lo), "=f"(hi) : "l"(v));
    return make_float2(lo, hi);
}

// smem layout (dynamic):
//   [0, 65536)        u64 wpack[512*16]  : BN-folded (w0'[2p][c], w0'[2p+1][c]), 128B rows
//   [65536, 67576)    float w1s[510]
//   [67576, 67644)    float b1s[17]
//   [67644, 67764)    float b0f[30]
#define SMEM_BYTES 67840

__global__ __launch_bounds__(TPB, 3) void fused_segnet_kernel(
    const float* __restrict__ x,
    const float* __restrict__ w0,
    const float* __restrict__ b0,
    const float* __restrict__ gamma,
    const float* __restrict__ beta,
    const float* __restrict__ mean,
    const float* __restrict__ var,
    const float* __restrict__ w1,
    const float* __restrict__ b1,
    float* __restrict__ dout,
    int write_logits)
{
    extern __shared__ unsigned char smem_raw[];
    u64*   wpack = (u64*)smem_raw;
    float* w1s   = (float*)(smem_raw + 65536);
    float* b1s   = w1s + 510;
    float* b0f   = b1s + NCLS;
    __shared__ float scale_s[CH];

    const int tid = threadIdx.x;

    // ---------- prologue: fold BN into conv0 weights/bias, stage small tensors ----------
    if (tid < CH) {
        float s = gamma[tid] * rsqrtf(var[tid] + BN_EPS);
        scale_s[tid] = s;
        b0f[tid] = (b0[tid] - mean[tid]) * s + beta[tid];
    }
    for (int i = tid; i < NCLS * CH; i += TPB) w1s[i] = w1[i];
    if (tid < NCLS) b1s[tid] = b1[tid];
    __syncthreads();

    for (int i = tid; i < CIN * NPAIR; i += TPB) {
        int c  = i / NPAIR;
        int po = i - c * NPAIR;
        int o0 = 2 * po, o1 = o0 + 1;
        wpack[(c << 4) + po] = pack2(w0[o0 * CIN + c] * scale_s[o0],
                                     w0[o1 * CIN + c] * scale_s[o1]);
    }
    __syncthreads();

    // ---------- mainloop: conv0 (512 -> 30), ONE pixel per thread ----------
    const int gp = blockIdx.x * TPB + tid;   // global pixel index, 0..131071
    const int b  = gp >> 14;                 // gp / HW
    const int hw = gp & (HW - 1);

    const float* xb = x + ((size_t)b * CIN) * HW + hw;

    // acc[po] packs output channels (2po, 2po+1) for this pixel
    u64 acc[NPAIR];
#pragma unroll
    for (int po = 0; po < NPAIR; po++)
        acc[po] = pack2(b0f[2 * po], b0f[2 * po + 1]);

    // register-resident x pipeline, PF channels deep
    float xbuf[PF];
#pragma unroll
    for (int i = 0; i < PF; i++)
        xbuf[i] = __ldcs(xb + (size_t)i * HW);

    for (int c0 = 0; c0 < CIN - PF; c0 += PF) {
#pragma unroll
        for (int i = 0; i < PF; i++) {
            const int c = c0 + i;
            float xv = xbuf[i];
            xbuf[i] = __ldcs(xb + (size_t)(c + PF) * HW);
            u64 d = dup2(xv);
            const u64* wr = wpack + (c << 4);
            const ulonglong2* wv = (const ulonglong2*)wr;
#pragma unroll
            for (int q = 0; q < 7; q++) {
                ulonglong2 w = wv[q];
                acc[2*q]   = fma2(w.x, d, acc[2*q]);
                acc[2*q+1] = fma2(w.y, d, acc[2*q+1]);
            }
            acc[14] = fma2(wr[14], d, acc[14]);
        }
    }
    {
        const int c0 = CIN - PF;
#pragma unroll
        for (int i = 0; i < PF; i++) {
            const int c = c0 + i;
            u64 d = dup2(xbuf[i]);
            const u64* wr = wpack + (c << 4);
            const ulonglong2* wv = (const ulonglong2*)wr;
#pragma unroll
            for (int q = 0; q < 7; q++) {
                ulonglong2 w = wv[q];
                acc[2*q]   = fma2(w.x, d, acc[2*q]);
                acc[2*q+1] = fma2(w.y, d, acc[2*q+1]);
            }
            acc[14] = fma2(wr[14], d, acc[14]);
        }
    }

    // ---------- epilogue: ReLU, conv1 (30 -> 17), argmax, stream logits ----------
    float h[CH];
#pragma unroll
    for (int po = 0; po < NPAIR; po++) {
        float2 a = unpack2(acc[po]);
        h[2 * po]     = fmaxf(a.x, 0.0f);
        h[2 * po + 1] = fmaxf(a.y, 0.0f);
    }

    float* lg = dout + (size_t)NBATCH * (NCLS * CH) * HW
                     + ((size_t)b * NCLS) * HW + hw;

    float best = -__builtin_huge_valf();
    int cls = 0;
#pragma unroll
    for (int k = 0; k < NCLS; k++) {
        float s = b1s[k];
#pragma unroll
        for (int j = 0; j < CH; j++)
            s = fmaf(w1s[k * CH + j], h[j], s);
        if (s > best) { best = s; cls = k; }    // strict > == first-max (jnp.argmax)
        if (write_logits)
            __stcs(lg + (size_t)k * HW, s);
    }

    // ---------- writes: res[b, k*30+j, hw] = (k==cls) * h[j] ----------
    float* res = dout + ((size_t)b * (NCLS * CH)) * HW + hw;
#pragma unroll
    for (int k = 0; k < NCLS; k++) {
        const bool m = (k == cls);
#pragma unroll
        for (int j = 0; j < CH; j++)
            __stcs(res + (size_t)(k * CH + j) * HW, m ? h[j] : 0.0f);
    }
}

extern "C" void kernel_launch(void* const* d_in, const int* in_sizes, int n_in,
                              void* d_out, int out_size)
{
    const float* x     = (const float*)d_in[0];
    const float* w0    = (const float*)d_in[1];
    const float* b0    = (const float*)d_in[2];
    const float* gamma = (const float*)d_in[3];
    const float* beta  = (const float*)d_in[4];
    const float* mean  = (const float*)d_in[5];
    const float* var   = (const float*)d_in[6];
    const float* w1    = (const float*)d_in[7];
    const float* b1    = (const float*)d_in[8];

    // d_out layout: res (8*510*128*128) followed by logits (8*17*128*128)
    const long long res_elems   = (long long)NBATCH * NCLS * CH * HW;
    const long long total_elems = res_elems + (long long)NBATCH * NCLS * HW;
    const int write_logits = ((long long)out_size >= total_elems) ? 1 : 0;

    static int smem_configured = 0;
    if (!smem_configured) {
        cudaFuncSetAttribute(fused_segnet_kernel,
                             cudaFuncAttributeMaxDynamicSharedMemorySize, SMEM_BYTES);
        smem_configured = 1;
    }

    const int n_pix  = NBATCH * HW;             // 131072
    const int blocks = n_pix / TPB;             // 512
    fused_segnet_kernel<<<blocks, TPB, SMEM_BYTES>>>(
        x, w0, b0, gamma, beta, mean, var, w1, b1, (float*)d_out, write_logits);
}